// round 14
// baseline (speedup 1.0000x reference)
#include <cuda_runtime.h>
#include <cuda_fp16.h>
#include <cstdint>
#include <math.h>

// ---------------- problem constants ----------------
#define B_    2
#define CIN   64
#define COUT  64
#define DIN   64
#define DOUT  62
#define KTAPS 27
#define EPS_  1e-8f

#define NCHUNK 54                  // 27 taps x {x, dx}, K=64 each
#define A_BYTES 16384              // 128 m x 64 k fp16
#define B_BYTES 16384              // 128 n x 64 k fp16
#define STAGE   (A_BYTES + B_BYTES)   // 32768
#define NSTAGE  3
#define SMEM_DYN (NSTAGE * STAGE)     // 98304 per CTA -> 2 CTAs/SM

#define NTILES  (31 * 62 * B_)        // 3844
#define NCTAS   296                   // 148 SMs x 2 CTAs

// ---------------- device scratch ----------------
__device__ float g_wnv[B_ * COUT * CIN * KTAPS];
__device__ float g_dwv[B_ * COUT * CIN * KTAPS];
// A tiles fp16, pre-swizzled [b][kind][tap] x (128 m x 64 k), row=128B,
// 16B-chunk c stored at c ^ (m&7)
__device__ __align__(16) __half g_Ah[B_ * 2 * KTAPS * 128 * 64];
// channel-last fp16 inputs [b][z][y][x][c] (row = 64 ch = 128B), + overread pad
__device__ __align__(16) __half g_xTh [B_ * DIN * DIN * DIN * CIN + 32768];
__device__ __align__(16) __half g_dxTh[B_ * DIN * DIN * DIN * CIN + 32768];

// ---------------- helpers ----------------
__device__ __forceinline__ uint32_t smem_u32(const void* p) {
    uint32_t a;
    asm("{ .reg .u64 t; cvta.to.shared.u64 t, %1; cvt.u32.u64 %0, t; }" : "=r"(a) : "l"(p));
    return a;
}
__device__ __forceinline__ void cp_async16(uint32_t dst, const void* src) {
    asm volatile("cp.async.cg.shared.global [%0], [%1], 16;" :: "r"(dst), "l"(src) : "memory");
}
#define LDMATRIX_X4(r0, r1, r2, r3, addr) \
    asm volatile("ldmatrix.sync.aligned.m8n8.x4.shared.b16 {%0,%1,%2,%3}, [%4];" \
        : "=r"(r0), "=r"(r1), "=r"(r2), "=r"(r3) : "r"(addr))

__device__ __forceinline__ void mma_f16(float* d, const uint32_t* a, const uint32_t* b2) {
    asm volatile(
        "mma.sync.aligned.m16n8k16.row.col.f32.f16.f16.f32 "
        "{%0,%1,%2,%3}, {%4,%5,%6,%7}, {%8,%9}, {%0,%1,%2,%3};"
        : "+f"(d[0]), "+f"(d[1]), "+f"(d[2]), "+f"(d[3])
        : "r"(a[0]), "r"(a[1]), "r"(a[2]), "r"(a[3]), "r"(b2[0]), "r"(b2[1]));
}

// ---------------------------------------------------------------------------
// Prep: style modulation + demodulation (validated round 2)
// ---------------------------------------------------------------------------
__global__ void prep_kernel(const float* __restrict__ s,
                            const float* __restrict__ style_weight,
                            const float* __restrict__ style_bias,
                            const float* __restrict__ weight)
{
    __shared__ float wsm[CIN * KTAPS];
    __shared__ float dwsm[CIN * KTAPS];
    __shared__ float red0[256];
    __shared__ float red1[256];

    const int b  = blockIdx.x >> 6;
    const int co = blockIdx.x & 63;
    const int tid = threadIdx.x;

    const float s0 = s[b * 2 + 0];
    const float s1 = s[b * 2 + 1];

    float sw2 = 0.f, swd = 0.f;
    for (int e = tid; e < CIN * KTAPS; e += 256) {
        const int ci = e / KTAPS;
        const float smod  = s0 * style_weight[ci * 2 + 0]
                          + s1 * style_weight[ci * 2 + 1]
                          + style_bias[ci];
        const float dsmod = style_weight[ci * 2 + 1];
        const float wt = weight[(co * CIN) * KTAPS + e];
        const float wv = wt * smod;
        const float dv = wt * dsmod;
        wsm[e]  = wv;
        dwsm[e] = dv;
        sw2 += wv * wv;
        swd += wv * dv;
    }
    red0[tid] = sw2;
    red1[tid] = swd;
    __syncthreads();
    for (int st = 128; st > 0; st >>= 1) {
        if (tid < st) { red0[tid] += red0[tid + st]; red1[tid] += red1[tid + st]; }
        __syncthreads();
    }
    const float norm  = sqrtf(red0[0] + EPS_);
    const float inv   = 1.0f / norm;
    const float dnorm = -red1[0] * inv * inv * inv;

    const size_t ob = (size_t)(b * COUT + co) * (CIN * KTAPS);
    for (int e = tid; e < CIN * KTAPS; e += 256) {
        g_wnv[ob + e] = wsm[e] * inv;
        g_dwv[ob + e] = dwsm[e] * inv + wsm[e] * dnorm;
    }
}

// ---------------------------------------------------------------------------
// Pack A tiles: fp16, [m=128][k=64] rows of 128B; 16B chunk (k>>3) stored at
// (k>>3) ^ (m&7)  ->  ldmatrix conflict-free.
//   kind 0 (B = x):  m<64 -> wn[co=m],  m>=64 -> dw[co=m-64]
//   kind 1 (B = dx): m<64 -> 0,         m>=64 -> wn[co=m-64]
// ---------------------------------------------------------------------------
__global__ void pack_kernel()
{
    const int blk  = blockIdx.x;
    const int t    = blk % KTAPS;
    const int kind = (blk / KTAPS) & 1;
    const int b    = blk / (2 * KTAPS);
    char* dst = (char*)g_Ah + (size_t)blk * A_BYTES;

    for (int e = threadIdx.x; e < 128 * 64; e += 256) {
        const int m = e >> 6;
        const int k = e & 63;
        float v = 0.f;
        if (kind == 0) {
            v = (m < 64)
              ? g_wnv[(size_t)(b * COUT + m)        * (CIN * KTAPS) + k * KTAPS + t]
              : g_dwv[(size_t)(b * COUT + (m - 64)) * (CIN * KTAPS) + k * KTAPS + t];
        } else if (m >= 64) {
            v = g_wnv[(size_t)(b * COUT + (m - 64)) * (CIN * KTAPS) + k * KTAPS + t];
        }
        const uint32_t off = (uint32_t)(m * 128 + (((k >> 3) ^ (m & 7)) << 4) + (k & 7) * 2);
        *(__half*)(dst + off) = __float2half_rn(v);
    }
}

// ---------------------------------------------------------------------------
// Transpose NCDHW -> fp16 channel-last [b][z][y][x][c].
// ---------------------------------------------------------------------------
__global__ void transpose_kernel(const float* __restrict__ x, const float* __restrict__ dx)
{
    __shared__ float tile[64][65];
    const int tx = threadIdx.x;            // 0..31
    const int ty = threadIdx.y;            // 0..7
    const int y = blockIdx.x, z = blockIdx.y, b = blockIdx.z;

    const size_t in_base = (size_t)(b * 64) * 262144 + (size_t)z * 4096 + (size_t)y * 64;
    const size_t r0 = (((size_t)(b * 64 + z)) * 64 + y) * 64;

    const float* srcs[2] = { x, dx };
    __half* dsts[2] = { g_xTh, g_dxTh };

    for (int pass = 0; pass < 2; pass++) {
        const float* src = srcs[pass];
        __half* dst = dsts[pass];
        __syncthreads();
        for (int c = ty; c < 64; c += 8) {
            tile[c][tx]      = src[in_base + (size_t)c * 262144 + tx];
            tile[c][tx + 32] = src[in_base + (size_t)c * 262144 + tx + 32];
        }
        __syncthreads();
        for (int xr = ty; xr < 64; xr += 8) {
            dst[(r0 + xr) * 64 + tx]      = __float2half_rn(tile[tx][xr]);
            dst[(r0 + xr) * 64 + tx + 32] = __float2half_rn(tile[tx + 32][xr]);
        }
    }
}

// ---------------------------------------------------------------------------
// Conv implicit-GEMM, fp16 mma.sync m16n8k16 + ldmatrix, 2 CTAs/SM,
// PERSISTENT: grid = 296 CTAs, each loops tiles (tile += 296) with the
// cp.async ring flowing continuously across tile boundaries (no re-prologue,
// no wave transitions).  Per tile: R12's proven body.
//  x-chunks (c<27):  8 warps (2M x 4N), warp m64 x n32, full M=128.
//  dx-chunks (c>=27): A rows 0..63 zero -> wm==0 warps idle (tensor work
//  is a shared SM resource; rebalancing doesn't reduce it — R13 lesson).
// Tile t -> yt = t%31, z0 = (t/31)%62, b = t/(31*62); y0 = yt*2.
// ---------------------------------------------------------------------------
__global__ __launch_bounds__(256, 2) void conv_mma_kernel(
    const float* __restrict__ bias, float* __restrict__ out)
{
    extern __shared__ __align__(16) char smem[];
    const uint32_t sb = smem_u32(smem);

    const int tid = threadIdx.x;
    const int wid = tid >> 5;
    const int lid = tid & 31;
    const int wm  = wid >> 2;          // M tile 0..1 (rows wm*64..)
    const int wn  = wid & 3;           // N tile 0..3 (cols wn*32..)
    const int g   = lid >> 2;          // 0..7
    const int ct  = lid & 3;           // 0..3

    // ---- per-thread ldmatrix row indices ----
    const int a_m  = wm * 64 + (lid & 7) + ((lid >> 3) & 1) * 8;  // + mi*16
    const int a_kq = (lid >> 4) & 1;
    const int b_n  = wn * 32 + (lid & 7) + ((lid >> 4) & 1) * 8;  // + q*16
    const int b_kq = (lid >> 3) & 1;

    // ---- hoisted smem staging dst offsets (chunk-invariant) ----
    uint32_t bDst[4];
    #pragma unroll
    for (int it = 0; it < 4; ++it) {
        const int i  = tid + it * 256;     // 0..1023
        const int n  = i >> 3;             // 0..127
        const int c8 = i & 7;
        bDst[it] = (uint32_t)(A_BYTES + n * 128 + ((c8 ^ (n & 7)) << 4));
    }
    const char* aBase = (const char*)g_Ah;

    // ---- stage-side state (leads compute by 2 chunks) ----
    int sTile = blockIdx.x;
    int sC    = 0;
    int sSlot = 0;

    // stage chunk sC of tile sTile into slot sSlot, then advance
    auto stage_next = [&]() {
        if (sTile < NTILES) {
            const int syt = sTile % 31;
            const int sz  = (sTile / 31) % 62;
            const int sbb = sTile / (31 * 62);
            const int c    = sC;
            const int kind = (c >= KTAPS) ? 1 : 0;
            const int t    = c - (kind ? KTAPS : 0);
            const int dz   = t / 9;
            const int r1   = t - dz * 9;
            const int dyy  = r1 / 3;
            const int dxx  = r1 - dyy * 3;
            const uint32_t d = sb + sSlot * STAGE;
            // A tile (pre-swizzled, linear copy); dx-chunks: rows 0..63 unused
            const char* srcA = aBase + (size_t)((sbb * 2 + kind) * KTAPS + t) * A_BYTES;
            const uint32_t aOff = (uint32_t)tid * 16;
            if (!kind) {
                cp_async16(d + aOff,        srcA + aOff);
                cp_async16(d + aOff + 4096, srcA + aOff + 4096);
            }
            cp_async16(d + aOff + 8192,  srcA + aOff + 8192);
            cp_async16(d + aOff + 12288, srcA + aOff + 12288);
            // B tile: im2col gather (128 rows x 128B)
            const int rb = (((sbb * 64 + sz + dz) * 64 + syt * 2 + dyy) * 64 + dxx);
            const char* srcB = (const char*)(kind ? g_dxTh : g_xTh) + (size_t)rb * 128;
            #pragma unroll
            for (int it = 0; it < 4; ++it) {
                const int i  = tid + it * 256;
                const int n  = i >> 3;
                const int c8 = i & 7;
                const uint32_t so = (uint32_t)((((n >> 6) * 64 + (n & 63)) * 128) + c8 * 16);
                cp_async16(d + bDst[it], srcB + so);
            }
        }
        if (++sC == NCHUNK) { sC = 0; sTile += NCTAS; }
        if (++sSlot == NSTAGE) sSlot = 0;
    };

    // ---- prologue: stage first 2 chunks ----
    stage_next(); asm volatile("cp.async.commit_group;" ::: "memory");
    stage_next(); asm volatile("cp.async.commit_group;" ::: "memory");

    int s0i = 0;                        // compute-side ring slot

    const size_t NOUT   = (size_t)DOUT * DOUT * DOUT;
    const size_t dy_off = (size_t)B_ * COUT * NOUT;
    const int m_base = wm * 64;
    const int n_base = wn * 32;

    for (int tile = blockIdx.x; tile < NTILES; tile += NCTAS) {
        float acc[4][4][4];
        #pragma unroll
        for (int mi = 0; mi < 4; ++mi)
            #pragma unroll
            for (int ni = 0; ni < 4; ++ni)
                #pragma unroll
                for (int j = 0; j < 4; ++j) acc[mi][ni][j] = 0.f;

        for (int c = 0; c < NCHUNK; ++c) {
            asm volatile("cp.async.wait_group %0;" :: "n"(NSTAGE - 2) : "memory");
            __syncthreads();
            stage_next();
            asm volatile("cp.async.commit_group;" ::: "memory");

            if (c < KTAPS || wm == 1) {
                const uint32_t As = sb + s0i * STAGE;
                const uint32_t Bs = As + A_BYTES;
                #pragma unroll
                for (int ks = 0; ks < 4; ++ks) {
                    const int kq_a = ks * 2 + a_kq;
                    const int kq_b = ks * 2 + b_kq;
                    uint32_t a[4][4];
                    #pragma unroll
                    for (int mi = 0; mi < 4; ++mi) {
                        const int m = a_m + mi * 16;
                        LDMATRIX_X4(a[mi][0], a[mi][1], a[mi][2], a[mi][3],
                                    As + m * 128 + ((kq_a ^ (m & 7)) << 4));
                    }
                    uint32_t bq[2][4];
                    #pragma unroll
                    for (int q = 0; q < 2; ++q) {
                        const int n = b_n + q * 16;
                        LDMATRIX_X4(bq[q][0], bq[q][1], bq[q][2], bq[q][3],
                                    Bs + n * 128 + ((kq_b ^ (n & 7)) << 4));
                    }
                    #pragma unroll
                    for (int mi = 0; mi < 4; ++mi)
                        #pragma unroll
                        for (int q = 0; q < 2; ++q) {
                            mma_f16(acc[mi][2 * q + 0], a[mi], &bq[q][0]);
                            mma_f16(acc[mi][2 * q + 1], a[mi], &bq[q][2]);
                        }
                }
            }
            if (++s0i == NSTAGE) s0i = 0;
        }

        // ---- epilogue for this tile (no smem use -> safe vs ring) ----
        const int yt = tile % 31;
        const int z0 = (tile / 31) % 62;
        const int bb = tile / (31 * 62);
        const int y0 = yt * 2;

        #pragma unroll
        for (int mi = 0; mi < 4; ++mi) {
            #pragma unroll
            for (int h = 0; h < 2; ++h) {
                const int m  = m_base + mi * 16 + h * 8 + g;
                const bool isy = (m < 64);
                const int co = m & 63;
                const float bv = isy ? bias[co] : 0.f;
                const size_t outadd = isy ? 0 : dy_off;
                const size_t ob = ((size_t)(bb * COUT + co) * DOUT + z0) * DOUT;
                #pragma unroll
                for (int ni = 0; ni < 4; ++ni) {
                    const int n  = n_base + ni * 8 + ct * 2;
                    const int yo = y0 + (n >> 6);       // < 62 always
                    const int xo = n & 63;
                    const size_t idx = (ob + yo) * DOUT + xo;
                    if (xo < DOUT) {
                        out[outadd + idx]     = acc[mi][ni][h * 2 + 0] + bv;
                        out[outadd + idx + 1] = acc[mi][ni][h * 2 + 1] + bv;  // xo even
                    }
                }
            }
        }
    }
}

// ---------------------------------------------------------------------------
// Launch. Inputs: x, s, dx, style_weight, style_bias, weight, bias.
// Output: concat(y, dy) fp32.
// ---------------------------------------------------------------------------
extern "C" void kernel_launch(void* const* d_in, const int* in_sizes, int n_in,
                              void* d_out, int out_size)
{
    const float* x    = (const float*)d_in[0];
    const float* s    = (const float*)d_in[1];
    const float* dx   = (const float*)d_in[2];
    const float* sw   = (const float*)d_in[3];
    const float* sb   = (const float*)d_in[4];
    const float* w    = (const float*)d_in[5];
    const float* bias = (const float*)d_in[6];
    float* out = (float*)d_out;

    cudaFuncSetAttribute(conv_mma_kernel, cudaFuncAttributeMaxDynamicSharedMemorySize, SMEM_DYN);

    prep_kernel<<<B_ * COUT, 256>>>(s, sw, sb, w);
    pack_kernel<<<B_ * 2 * KTAPS, 256>>>();
    transpose_kernel<<<dim3(64, 64, B_), dim3(32, 8)>>>(x, dx);
    conv_mma_kernel<<<NCTAS, 256, SMEM_DYN>>>(bias, out);
}

// round 15
// speedup vs baseline: 1.1648x; 1.1648x over previous
#include <cuda_runtime.h>
#include <cuda_fp16.h>
#include <cstdint>
#include <math.h>

// ---------------- problem constants ----------------
#define B_    2
#define CIN   64
#define COUT  64
#define DIN   64
#define DOUT  62
#define KTAPS 27
#define EPS_  1e-8f

#define A_BYTES 16384              // 128 m x 64 k fp16 (x-path A tile)
// merged-stage layout: A_x | A_dx(rows 64..127) | B_x | B_dx
#define OFF_ADX 16384
#define OFF_BX  24576
#define OFF_BDX 40960
#define STAGE   57344              // 56 KB
#define NSTAGE  2
#define SMEM_DYN (NSTAGE * STAGE)  // 114688 per CTA -> 2 CTAs/SM (226KB/228KB)

// ---------------- device scratch ----------------
__device__ float g_wnv[B_ * COUT * CIN * KTAPS];
__device__ float g_dwv[B_ * COUT * CIN * KTAPS];
// A tiles fp16, pre-swizzled [b][kind][tap] x (128 m x 64 k), row=128B,
// 16B-chunk c stored at c ^ (m&7)
__device__ __align__(16) __half g_Ah[B_ * 2 * KTAPS * 128 * 64];
// channel-last fp16 inputs [b][z][y][x][c] (row = 64 ch = 128B), + overread pad
__device__ __align__(16) __half g_xTh [B_ * DIN * DIN * DIN * CIN + 32768];
__device__ __align__(16) __half g_dxTh[B_ * DIN * DIN * DIN * CIN + 32768];

// ---------------- helpers ----------------
__device__ __forceinline__ uint32_t smem_u32(const void* p) {
    uint32_t a;
    asm("{ .reg .u64 t; cvta.to.shared.u64 t, %1; cvt.u32.u64 %0, t; }" : "=r"(a) : "l"(p));
    return a;
}
__device__ __forceinline__ void cp_async16(uint32_t dst, const void* src) {
    asm volatile("cp.async.cg.shared.global [%0], [%1], 16;" :: "r"(dst), "l"(src) : "memory");
}
#define LDMATRIX_X4(r0, r1, r2, r3, addr) \
    asm volatile("ldmatrix.sync.aligned.m8n8.x4.shared.b16 {%0,%1,%2,%3}, [%4];" \
        : "=r"(r0), "=r"(r1), "=r"(r2), "=r"(r3) : "r"(addr))

__device__ __forceinline__ void mma_f16(float* d, const uint32_t* a, const uint32_t* b2) {
    asm volatile(
        "mma.sync.aligned.m16n8k16.row.col.f32.f16.f16.f32 "
        "{%0,%1,%2,%3}, {%4,%5,%6,%7}, {%8,%9}, {%0,%1,%2,%3};"
        : "+f"(d[0]), "+f"(d[1]), "+f"(d[2]), "+f"(d[3])
        : "r"(a[0]), "r"(a[1]), "r"(a[2]), "r"(a[3]), "r"(b2[0]), "r"(b2[1]));
}

// ---------------------------------------------------------------------------
// Prep: style modulation + demodulation (validated round 2)
// ---------------------------------------------------------------------------
__global__ void prep_kernel(const float* __restrict__ s,
                            const float* __restrict__ style_weight,
                            const float* __restrict__ style_bias,
                            const float* __restrict__ weight)
{
    __shared__ float wsm[CIN * KTAPS];
    __shared__ float dwsm[CIN * KTAPS];
    __shared__ float red0[256];
    __shared__ float red1[256];

    const int b  = blockIdx.x >> 6;
    const int co = blockIdx.x & 63;
    const int tid = threadIdx.x;

    const float s0 = s[b * 2 + 0];
    const float s1 = s[b * 2 + 1];

    float sw2 = 0.f, swd = 0.f;
    for (int e = tid; e < CIN * KTAPS; e += 256) {
        const int ci = e / KTAPS;
        const float smod  = s0 * style_weight[ci * 2 + 0]
                          + s1 * style_weight[ci * 2 + 1]
                          + style_bias[ci];
        const float dsmod = style_weight[ci * 2 + 1];
        const float wt = weight[(co * CIN) * KTAPS + e];
        const float wv = wt * smod;
        const float dv = wt * dsmod;
        wsm[e]  = wv;
        dwsm[e] = dv;
        sw2 += wv * wv;
        swd += wv * dv;
    }
    red0[tid] = sw2;
    red1[tid] = swd;
    __syncthreads();
    for (int st = 128; st > 0; st >>= 1) {
        if (tid < st) { red0[tid] += red0[tid + st]; red1[tid] += red1[tid + st]; }
        __syncthreads();
    }
    const float norm  = sqrtf(red0[0] + EPS_);
    const float inv   = 1.0f / norm;
    const float dnorm = -red1[0] * inv * inv * inv;

    const size_t ob = (size_t)(b * COUT + co) * (CIN * KTAPS);
    for (int e = tid; e < CIN * KTAPS; e += 256) {
        g_wnv[ob + e] = wsm[e] * inv;
        g_dwv[ob + e] = dwsm[e] * inv + wsm[e] * dnorm;
    }
}

// ---------------------------------------------------------------------------
// Pack A tiles: fp16, [m=128][k=64] rows of 128B; 16B chunk (k>>3) stored at
// (k>>3) ^ (m&7)  ->  ldmatrix conflict-free.
//   kind 0 (B = x):  m<64 -> wn[co=m],  m>=64 -> dw[co=m-64]
//   kind 1 (B = dx): m<64 -> 0,         m>=64 -> wn[co=m-64]
// ---------------------------------------------------------------------------
__global__ void pack_kernel()
{
    const int blk  = blockIdx.x;
    const int t    = blk % KTAPS;
    const int kind = (blk / KTAPS) & 1;
    const int b    = blk / (2 * KTAPS);
    char* dst = (char*)g_Ah + (size_t)blk * A_BYTES;

    for (int e = threadIdx.x; e < 128 * 64; e += 256) {
        const int m = e >> 6;
        const int k = e & 63;
        float v = 0.f;
        if (kind == 0) {
            v = (m < 64)
              ? g_wnv[(size_t)(b * COUT + m)        * (CIN * KTAPS) + k * KTAPS + t]
              : g_dwv[(size_t)(b * COUT + (m - 64)) * (CIN * KTAPS) + k * KTAPS + t];
        } else if (m >= 64) {
            v = g_wnv[(size_t)(b * COUT + (m - 64)) * (CIN * KTAPS) + k * KTAPS + t];
        }
        const uint32_t off = (uint32_t)(m * 128 + (((k >> 3) ^ (m & 7)) << 4) + (k & 7) * 2);
        *(__half*)(dst + off) = __float2half_rn(v);
    }
}

// ---------------------------------------------------------------------------
// Transpose NCDHW -> fp16 channel-last [b][z][y][x][c].
// ---------------------------------------------------------------------------
__global__ void transpose_kernel(const float* __restrict__ x, const float* __restrict__ dx)
{
    __shared__ float tile[64][65];
    const int tx = threadIdx.x;            // 0..31
    const int ty = threadIdx.y;            // 0..7
    const int y = blockIdx.x, z = blockIdx.y, b = blockIdx.z;

    const size_t in_base = (size_t)(b * 64) * 262144 + (size_t)z * 4096 + (size_t)y * 64;
    const size_t r0 = (((size_t)(b * 64 + z)) * 64 + y) * 64;

    const float* srcs[2] = { x, dx };
    __half* dsts[2] = { g_xTh, g_dxTh };

    for (int pass = 0; pass < 2; pass++) {
        const float* src = srcs[pass];
        __half* dst = dsts[pass];
        __syncthreads();
        for (int c = ty; c < 64; c += 8) {
            tile[c][tx]      = src[in_base + (size_t)c * 262144 + tx];
            tile[c][tx + 32] = src[in_base + (size_t)c * 262144 + tx + 32];
        }
        __syncthreads();
        for (int xr = ty; xr < 64; xr += 8) {
            dst[(r0 + xr) * 64 + tx]      = __float2half_rn(tile[tx][xr]);
            dst[(r0 + xr) * 64 + tx + 32] = __float2half_rn(tile[tx + 32][xr]);
        }
    }
}

// ---------------------------------------------------------------------------
// Conv implicit-GEMM, fp16 mma.sync m16n8k16 + ldmatrix, 2 CTAs/SM.
// CTA tile M=128 x N=128, 256 threads = 8 warps (2M x 4N), warp m64 x n32.
// MERGED intervals: each of the 27 taps stages x-A, dx-A(upper), x-B, dx-B
// together (56KB) in a 2-stage ring -> 27 barriers/tile instead of 54.
// Per interval: all warps do the x GEMM (full M=128); wm==1 warps then do
// the dx GEMM (dy rows only), accumulating into the same dy accumulators.
// Grid (31 ytiles, 62 z, 2 b) = 3844 CTAs -> 296 concurrent, ~13 even waves.
// ---------------------------------------------------------------------------
__global__ __launch_bounds__(256, 2) void conv_mma_kernel(
    const float* __restrict__ bias, float* __restrict__ out)
{
    extern __shared__ __align__(16) char smem[];
    const uint32_t sb = smem_u32(smem);

    const int tid = threadIdx.x;
    const int wid = tid >> 5;
    const int lid = tid & 31;
    const int wm  = wid >> 2;          // M tile 0..1 (rows wm*64..)
    const int wn  = wid & 3;           // N tile 0..3 (cols wn*32..)
    const int g   = lid >> 2;          // 0..7
    const int ct  = lid & 3;           // 0..3

    const int y0 = blockIdx.x * 2;     // 2 output rows per CTA (62 = 31*2)
    const int z0 = blockIdx.y;
    const int b  = blockIdx.z;

    float acc[4][4][4];
    #pragma unroll
    for (int mi = 0; mi < 4; ++mi)
        #pragma unroll
        for (int ni = 0; ni < 4; ++ni)
            #pragma unroll
            for (int j = 0; j < 4; ++j) acc[mi][ni][j] = 0.f;

    // ---- per-thread ldmatrix row indices ----
    const int a_row = (lid & 7) + ((lid >> 3) & 1) * 8;   // 0..15
    const int a_m   = wm * 64 + a_row;                     // x GEMM, + mi*16
    const int a_kq  = (lid >> 4) & 1;
    const int b_n   = wn * 32 + (lid & 7) + ((lid >> 4) & 1) * 8;  // + q*16
    const int b_kq  = (lid >> 3) & 1;

    // ---- hoisted staging offsets (interval-invariant) ----
    uint32_t bOff[4];                  // dst offset within a B tile
    uint32_t bSrc[4];                  // src offset within the gathered rows
    #pragma unroll
    for (int it = 0; it < 4; ++it) {
        const int i  = tid + it * 256;     // 0..1023
        const int n  = i >> 3;             // 0..127
        const int c8 = i & 7;
        bOff[it] = (uint32_t)(n * 128 + ((c8 ^ (n & 7)) << 4));
        bSrc[it] = (uint32_t)((((n >> 6) * 64 + (n & 63)) * 128) + c8 * 16);
    }
    const int rb0 = ((b * 64 + z0) * 64 + y0) * 64;
    const char* xB  = (const char*)g_xTh  + (size_t)rb0 * 128;
    const char* dxB = (const char*)g_dxTh + (size_t)rb0 * 128;
    const char* aBaseX  = (const char*)g_Ah + (size_t)(b * 2)     * KTAPS * A_BYTES;
    const char* aBaseDX = (const char*)g_Ah + (size_t)(b * 2 + 1) * KTAPS * A_BYTES;

    // ---- staging: tap t (both kinds) into ring slot s ----
    auto stage = [&](int t, int s) {
        const int dz   = t / 9;
        const int r1   = t - dz * 9;
        const int dyy  = r1 / 3;
        const int dxx  = r1 - dyy * 3;
        const uint32_t d = sb + s * STAGE;
        const uint32_t aOff = (uint32_t)tid * 16;
        // A_x tile: 16KB pre-swizzled linear copy
        const char* srcAx = aBaseX + (size_t)t * A_BYTES;
        cp_async16(d + aOff,         srcAx + aOff);
        cp_async16(d + aOff + 4096,  srcAx + aOff + 4096);
        cp_async16(d + aOff + 8192,  srcAx + aOff + 8192);
        cp_async16(d + aOff + 12288, srcAx + aOff + 12288);
        // A_dx tile: rows 64..127 only (8KB), preserves ^(m&7) swizzle
        const char* srcAdx = aBaseDX + (size_t)t * A_BYTES + 8192;
        cp_async16(d + OFF_ADX + aOff,        srcAdx + aOff);
        cp_async16(d + OFF_ADX + aOff + 4096, srcAdx + aOff + 4096);
        // B tiles: im2col gather (128 rows x 128B each)
        const size_t gOff = (size_t)(dz * 4096 + dyy * 64 + dxx) * 128;
        const char* srcBx  = xB  + gOff;
        const char* srcBdx = dxB + gOff;
        #pragma unroll
        for (int it = 0; it < 4; ++it) {
            cp_async16(d + OFF_BX  + bOff[it], srcBx  + bSrc[it]);
            cp_async16(d + OFF_BDX + bOff[it], srcBdx + bSrc[it]);
        }
    };

    // ---- prologue: stage tap 0 ----
    stage(0, 0); asm volatile("cp.async.commit_group;" ::: "memory");

    for (int t = 0; t < KTAPS; ++t) {
        // all outstanding copies done -> tap t fully resident
        asm volatile("cp.async.wait_group 0;" ::: "memory");
        __syncthreads();
        if (t + 1 < KTAPS) stage(t + 1, (t + 1) & 1);
        asm volatile("cp.async.commit_group;" ::: "memory");

        const uint32_t As  = sb + (t & 1) * STAGE;
        const uint32_t Bs  = As + OFF_BX;
        // ---- x GEMM: full M=128, all warps ----
        #pragma unroll
        for (int ks = 0; ks < 4; ++ks) {
            const int kq_a = ks * 2 + a_kq;
            const int kq_b = ks * 2 + b_kq;
            uint32_t a[4][4];
            #pragma unroll
            for (int mi = 0; mi < 4; ++mi) {
                const int m = a_m + mi * 16;
                LDMATRIX_X4(a[mi][0], a[mi][1], a[mi][2], a[mi][3],
                            As + m * 128 + ((kq_a ^ (m & 7)) << 4));
            }
            uint32_t bq[2][4];
            #pragma unroll
            for (int q = 0; q < 2; ++q) {
                const int n = b_n + q * 16;
                LDMATRIX_X4(bq[q][0], bq[q][1], bq[q][2], bq[q][3],
                            Bs + n * 128 + ((kq_b ^ (n & 7)) << 4));
            }
            #pragma unroll
            for (int mi = 0; mi < 4; ++mi)
                #pragma unroll
                for (int q = 0; q < 2; ++q) {
                    mma_f16(acc[mi][2 * q + 0], a[mi], &bq[q][0]);
                    mma_f16(acc[mi][2 * q + 1], a[mi], &bq[q][2]);
                }
        }
        // ---- dx GEMM: dy rows only (wm==1 warps), same accumulators ----
        if (wm == 1) {
            const uint32_t Asd = As + OFF_ADX;
            const uint32_t Bsd = As + OFF_BDX;
            #pragma unroll
            for (int ks = 0; ks < 4; ++ks) {
                const int kq_a = ks * 2 + a_kq;
                const int kq_b = ks * 2 + b_kq;
                uint32_t a[4][4];
                #pragma unroll
                for (int mi = 0; mi < 4; ++mi) {
                    const int r = a_row + mi * 16;           // row-64 index
                    LDMATRIX_X4(a[mi][0], a[mi][1], a[mi][2], a[mi][3],
                                Asd + r * 128 + ((kq_a ^ (r & 7)) << 4));
                }
                uint32_t bq[2][4];
                #pragma unroll
                for (int q = 0; q < 2; ++q) {
                    const int n = b_n + q * 16;
                    LDMATRIX_X4(bq[q][0], bq[q][1], bq[q][2], bq[q][3],
                                Bsd + n * 128 + ((kq_b ^ (n & 7)) << 4));
                }
                #pragma unroll
                for (int mi = 0; mi < 4; ++mi)
                    #pragma unroll
                    for (int q = 0; q < 2; ++q) {
                        mma_f16(acc[mi][2 * q + 0], a[mi], &bq[q][0]);
                        mma_f16(acc[mi][2 * q + 1], a[mi], &bq[q][2]);
                    }
            }
        }
    }

    // ---- epilogue ----
    const size_t NOUT   = (size_t)DOUT * DOUT * DOUT;
    const size_t dy_off = (size_t)B_ * COUT * NOUT;
    const int m_base = wm * 64;
    const int n_base = wn * 32;

    #pragma unroll
    for (int mi = 0; mi < 4; ++mi) {
        #pragma unroll
        for (int h = 0; h < 2; ++h) {
            const int m  = m_base + mi * 16 + h * 8 + g;
            const bool isy = (m < 64);
            const int co = m & 63;
            const float bv = isy ? bias[co] : 0.f;
            const size_t outadd = isy ? 0 : dy_off;
            const size_t ob = ((size_t)(b * COUT + co) * DOUT + z0) * DOUT;
            #pragma unroll
            for (int ni = 0; ni < 4; ++ni) {
                const int n  = n_base + ni * 8 + ct * 2;
                const int yo = y0 + (n >> 6);       // < 62 always (31*2 grid)
                const int xo = n & 63;
                const size_t idx = (ob + yo) * DOUT + xo;
                if (xo < DOUT) {
                    out[outadd + idx]     = acc[mi][ni][h * 2 + 0] + bv;
                    out[outadd + idx + 1] = acc[mi][ni][h * 2 + 1] + bv;  // xo even
                }
            }
        }
    }
}

// ---------------------------------------------------------------------------
// Launch. Inputs: x, s, dx, style_weight, style_bias, weight, bias.
// Output: concat(y, dy) fp32.
// ---------------------------------------------------------------------------
extern "C" void kernel_launch(void* const* d_in, const int* in_sizes, int n_in,
                              void* d_out, int out_size)
{
    const float* x    = (const float*)d_in[0];
    const float* s    = (const float*)d_in[1];
    const float* dx   = (const float*)d_in[2];
    const float* sw   = (const float*)d_in[3];
    const float* sb   = (const float*)d_in[4];
    const float* w    = (const float*)d_in[5];
    const float* bias = (const float*)d_in[6];
    float* out = (float*)d_out;

    cudaFuncSetAttribute(conv_mma_kernel, cudaFuncAttributeMaxDynamicSharedMemorySize, SMEM_DYN);

    prep_kernel<<<B_ * COUT, 256>>>(s, sw, sb, w);
    pack_kernel<<<B_ * 2 * KTAPS, 256>>>();
    transpose_kernel<<<dim3(64, 64, B_), dim3(32, 8)>>>(x, dx);
    conv_mma_kernel<<<dim3(31, 62, B_), 256, SMEM_DYN>>>(bias, out);
}

// round 16
// speedup vs baseline: 1.1744x; 1.0083x over previous
#include <cuda_runtime.h>
#include <cuda_fp16.h>
#include <cstdint>
#include <math.h>

// ---------------- problem constants ----------------
#define B_    2
#define CIN   64
#define COUT  64
#define DIN   64
#define DOUT  62
#define KTAPS 27
#define EPS_  1e-8f

#define A_BYTES 16384              // 128 m x 64 k fp16 (x-path A tile)
// merged-stage layout: A_x | A_dx(rows 64..127) | B_x | B_dx
#define OFF_ADX 16384
#define OFF_BX  24576
#define OFF_BDX 40960
#define STAGE   57344              // 56 KB
#define NSTAGE  2
#define SMEM_DYN (NSTAGE * STAGE)  // 114688 per CTA -> 2 CTAs/SM

// ---------------- device scratch ----------------
// A tiles fp16, pre-swizzled [b][kind][tap] x (128 m x 64 k), row=128B,
// 16B-chunk c stored at c ^ (m&7)
__device__ __align__(16) __half g_Ah[B_ * 2 * KTAPS * 128 * 64];
// channel-last fp16 inputs [b][z][y][x][c] (row = 64 ch = 128B), + overread pad
__device__ __align__(16) __half g_xTh [B_ * DIN * DIN * DIN * CIN + 32768];
__device__ __align__(16) __half g_dxTh[B_ * DIN * DIN * DIN * CIN + 32768];

// byte offset of tap t into the gathered input rows:
// (dz*4096 + dyy*64 + dxx) * 128, t = dz*9 + dyy*3 + dxx
__device__ const uint32_t g_tapOff[KTAPS] = {
          0,     128,     256,    8192,    8320,    8448,   16384,   16512,   16640,
     524288,  524416,  524544,  532480,  532608,  532736,  540672,  540800,  540928,
    1048576, 1048704, 1048832, 1056768, 1056896, 1057024, 1064960, 1065088, 1065216
};

// ---------------- helpers ----------------
__device__ __forceinline__ uint32_t smem_u32(const void* p) {
    uint32_t a;
    asm("{ .reg .u64 t; cvta.to.shared.u64 t, %1; cvt.u32.u64 %0, t; }" : "=r"(a) : "l"(p));
    return a;
}
__device__ __forceinline__ void cp_async16(uint32_t dst, const void* src) {
    asm volatile("cp.async.cg.shared.global [%0], [%1], 16;" :: "r"(dst), "l"(src) : "memory");
}
#define LDMATRIX_X4(r0, r1, r2, r3, addr) \
    asm volatile("ldmatrix.sync.aligned.m8n8.x4.shared.b16 {%0,%1,%2,%3}, [%4];" \
        : "=r"(r0), "=r"(r1), "=r"(r2), "=r"(r3) : "r"(addr))

__device__ __forceinline__ void mma_f16(float* d, const uint32_t* a, const uint32_t* b2) {
    asm volatile(
        "mma.sync.aligned.m16n8k16.row.col.f32.f16.f16.f32 "
        "{%0,%1,%2,%3}, {%4,%5,%6,%7}, {%8,%9}, {%0,%1,%2,%3};"
        : "+f"(d[0]), "+f"(d[1]), "+f"(d[2]), "+f"(d[3])
        : "r"(a[0]), "r"(a[1]), "r"(a[2]), "r"(a[3]), "r"(b2[0]), "r"(b2[1]));
}

// ---------------------------------------------------------------------------
// Prep + pack fused: one block per (b, co).  Computes modulation/demodulation
// (validated round 2) and writes fp16 A tiles directly, pre-swizzled:
//   kind 0 tile t: row co -> wn,  row co+64 -> dw
//   kind 1 tile t: row co+64 -> wn          (row co..: zero-filled separately)
// ---------------------------------------------------------------------------
__global__ void prep_kernel(const float* __restrict__ s,
                            const float* __restrict__ style_weight,
                            const float* __restrict__ style_bias,
                            const float* __restrict__ weight)
{
    __shared__ float wsm[CIN * KTAPS];
    __shared__ float dwsm[CIN * KTAPS];
    __shared__ float red0[256];
    __shared__ float red1[256];

    const int b  = blockIdx.x >> 6;
    const int co = blockIdx.x & 63;
    const int tid = threadIdx.x;

    const float s0 = s[b * 2 + 0];
    const float s1 = s[b * 2 + 1];

    float sw2 = 0.f, swd = 0.f;
    for (int e = tid; e < CIN * KTAPS; e += 256) {
        const int ci = e / KTAPS;
        const float smod  = s0 * style_weight[ci * 2 + 0]
                          + s1 * style_weight[ci * 2 + 1]
                          + style_bias[ci];
        const float dsmod = style_weight[ci * 2 + 1];
        const float wt = weight[(co * CIN) * KTAPS + e];
        const float wv = wt * smod;
        const float dv = wt * dsmod;
        wsm[e]  = wv;
        dwsm[e] = dv;
        sw2 += wv * wv;
        swd += wv * dv;
    }
    red0[tid] = sw2;
    red1[tid] = swd;
    __syncthreads();
    for (int st = 128; st > 0; st >>= 1) {
        if (tid < st) { red0[tid] += red0[tid + st]; red1[tid] += red1[tid + st]; }
        __syncthreads();
    }
    const float norm  = sqrtf(red0[0] + EPS_);
    const float inv   = 1.0f / norm;
    const float dnorm = -red1[0] * inv * inv * inv;

    char* dst = (char*)g_Ah;
    const size_t base0 = (size_t)((b * 2 + 0) * KTAPS) * A_BYTES;
    const size_t base1 = (size_t)((b * 2 + 1) * KTAPS) * A_BYTES;
    const int sw = co & 7;

    for (int e = tid; e < CIN * KTAPS; e += 256) {
        const int ci = e / KTAPS;
        const int t  = e - ci * KTAPS;
        const float wn = wsm[e] * inv;
        const float dw = dwsm[e] * inv + wsm[e] * dnorm;
        const uint32_t kpart = ((((uint32_t)(ci >> 3)) ^ sw) << 4) + (ci & 7) * 2;
        const uint32_t offL = (uint32_t)co * 128 + kpart;          // row co
        const uint32_t offH = (uint32_t)(co + 64) * 128 + kpart;   // row co+64
        const size_t tb0 = base0 + (size_t)t * A_BYTES;
        const size_t tb1 = base1 + (size_t)t * A_BYTES;
        *(__half*)(dst + tb0 + offL) = __float2half_rn(wn);
        *(__half*)(dst + tb0 + offH) = __float2half_rn(dw);
        *(__half*)(dst + tb1 + offH) = __float2half_rn(wn);
    }
}

// Zero the unused lower halves (rows 0..63) of the kind-1 A tiles.
// (They are staged but never read; zero keeps any stray read harmless.)
__global__ void zero_adx_kernel()
{
    const int blk = blockIdx.x;            // b*27 + t
    const int t   = blk % KTAPS;
    const int b   = blk / KTAPS;
    float4* dst = (float4*)((char*)g_Ah
        + (size_t)((b * 2 + 1) * KTAPS + t) * A_BYTES);
    for (int i = threadIdx.x; i < 8192 / 16; i += 256)
        dst[i] = make_float4(0.f, 0.f, 0.f, 0.f);
}

// ---------------------------------------------------------------------------
// Transpose NCDHW -> fp16 channel-last [b][z][y][x][c].  half2 stores.
// ---------------------------------------------------------------------------
__global__ void transpose_kernel(const float* __restrict__ x, const float* __restrict__ dx)
{
    __shared__ float tile[64][65];
    const int tx = threadIdx.x;            // 0..31
    const int ty = threadIdx.y;            // 0..7
    const int y = blockIdx.x, z = blockIdx.y, b = blockIdx.z;

    const size_t in_base = (size_t)(b * 64) * 262144 + (size_t)z * 4096 + (size_t)y * 64;
    const size_t r0 = (((size_t)(b * 64 + z)) * 64 + y) * 64;

    const float* srcs[2] = { x, dx };
    __half* dsts[2] = { g_xTh, g_dxTh };

    for (int pass = 0; pass < 2; pass++) {
        const float* src = srcs[pass];
        __half* dst = dsts[pass];
        __syncthreads();
        for (int c = ty; c < 64; c += 8) {
            tile[c][tx]      = src[in_base + (size_t)c * 262144 + tx];
            tile[c][tx + 32] = src[in_base + (size_t)c * 262144 + tx + 32];
        }
        __syncthreads();
        for (int xr = ty; xr < 64; xr += 8) {
            const __half2 h = __floats2half2_rn(tile[2 * tx][xr], tile[2 * tx + 1][xr]);
            *(__half2*)(dst + (r0 + xr) * 64 + 2 * tx) = h;
        }
    }
}

// ---------------------------------------------------------------------------
// Conv implicit-GEMM, fp16 mma.sync m16n8k16 + ldmatrix, 2 CTAs/SM.
// CTA tile M=128 x N=128, 256 threads = 8 warps (2M x 4N), warp m64 x n32.
// MERGED intervals: each of the 27 taps stages x-A, dx-A(upper), x-B, dx-B
// together (56KB) in a 2-stage ring -> 27 barriers/tile.
// Tap gather offsets come from g_tapOff (no divides in the mainloop).
// Per interval: all warps do the x GEMM (full M=128); wm==1 warps then do
// the dx GEMM (dy rows only), accumulating into the same dy accumulators.
// Grid (31 ytiles, 62 z, 2 b) = 3844 CTAs -> 296 concurrent, ~13 even waves.
// ---------------------------------------------------------------------------
__global__ __launch_bounds__(256, 2) void conv_mma_kernel(
    const float* __restrict__ bias, float* __restrict__ out)
{
    extern __shared__ __align__(16) char smem[];
    const uint32_t sb = smem_u32(smem);

    const int tid = threadIdx.x;
    const int wid = tid >> 5;
    const int lid = tid & 31;
    const int wm  = wid >> 2;          // M tile 0..1 (rows wm*64..)
    const int wn  = wid & 3;           // N tile 0..3 (cols wn*32..)
    const int g   = lid >> 2;          // 0..7
    const int ct  = lid & 3;           // 0..3

    const int y0 = blockIdx.x * 2;     // 2 output rows per CTA (62 = 31*2)
    const int z0 = blockIdx.y;
    const int b  = blockIdx.z;

    float acc[4][4][4];
    #pragma unroll
    for (int mi = 0; mi < 4; ++mi)
        #pragma unroll
        for (int ni = 0; ni < 4; ++ni)
            #pragma unroll
            for (int j = 0; j < 4; ++j) acc[mi][ni][j] = 0.f;

    // ---- per-thread ldmatrix row indices ----
    const int a_row = (lid & 7) + ((lid >> 3) & 1) * 8;   // 0..15
    const int a_m   = wm * 64 + a_row;                     // x GEMM, + mi*16
    const int a_kq  = (lid >> 4) & 1;
    const int b_n   = wn * 32 + (lid & 7) + ((lid >> 4) & 1) * 8;  // + q*16
    const int b_kq  = (lid >> 3) & 1;

    // ---- hoisted staging offsets (interval-invariant) ----
    uint32_t bOff[4];                  // dst offset within a B tile
    uint32_t bSrc[4];                  // src offset within the gathered rows
    #pragma unroll
    for (int it = 0; it < 4; ++it) {
        const int i  = tid + it * 256;     // 0..1023
        const int n  = i >> 3;             // 0..127
        const int c8 = i & 7;
        bOff[it] = (uint32_t)(n * 128 + ((c8 ^ (n & 7)) << 4));
        bSrc[it] = (uint32_t)((((n >> 6) * 64 + (n & 63)) * 128) + c8 * 16);
    }
    const int rb0 = ((b * 64 + z0) * 64 + y0) * 64;
    const char* xB  = (const char*)g_xTh  + (size_t)rb0 * 128;
    const char* dxB = (const char*)g_dxTh + (size_t)rb0 * 128;
    const char* aBaseX  = (const char*)g_Ah + (size_t)(b * 2)     * KTAPS * A_BYTES;
    const char* aBaseDX = (const char*)g_Ah + (size_t)(b * 2 + 1) * KTAPS * A_BYTES;

    // ---- staging: tap t (both kinds) into ring slot s ----
    auto stage = [&](int t, int s) {
        const uint32_t d = sb + s * STAGE;
        const uint32_t aOff = (uint32_t)tid * 16;
        // A_x tile: 16KB pre-swizzled linear copy
        const char* srcAx = aBaseX + (size_t)t * A_BYTES;
        cp_async16(d + aOff,         srcAx + aOff);
        cp_async16(d + aOff + 4096,  srcAx + aOff + 4096);
        cp_async16(d + aOff + 8192,  srcAx + aOff + 8192);
        cp_async16(d + aOff + 12288, srcAx + aOff + 12288);
        // A_dx tile: rows 64..127 only (8KB), preserves ^(m&7) swizzle
        const char* srcAdx = aBaseDX + (size_t)t * A_BYTES + 8192;
        cp_async16(d + OFF_ADX + aOff,        srcAdx + aOff);
        cp_async16(d + OFF_ADX + aOff + 4096, srcAdx + aOff + 4096);
        // B tiles: im2col gather (128 rows x 128B each); tap offset from table
        const size_t gOff = g_tapOff[t];
        const char* srcBx  = xB  + gOff;
        const char* srcBdx = dxB + gOff;
        #pragma unroll
        for (int it = 0; it < 4; ++it) {
            cp_async16(d + OFF_BX  + bOff[it], srcBx  + bSrc[it]);
            cp_async16(d + OFF_BDX + bOff[it], srcBdx + bSrc[it]);
        }
    };

    // ---- prologue: stage tap 0 ----
    stage(0, 0); asm volatile("cp.async.commit_group;" ::: "memory");

    for (int t = 0; t < KTAPS; ++t) {
        // all outstanding copies done -> tap t fully resident
        asm volatile("cp.async.wait_group 0;" ::: "memory");
        __syncthreads();
        if (t + 1 < KTAPS) stage(t + 1, (t + 1) & 1);
        asm volatile("cp.async.commit_group;" ::: "memory");

        const uint32_t As  = sb + (t & 1) * STAGE;
        const uint32_t Bs  = As + OFF_BX;
        // ---- x GEMM: full M=128, all warps ----
        #pragma unroll
        for (int ks = 0; ks < 4; ++ks) {
            const int kq_a = ks * 2 + a_kq;
            const int kq_b = ks * 2 + b_kq;
            uint32_t a[4][4];
            #pragma unroll
            for (int mi = 0; mi < 4; ++mi) {
                const int m = a_m + mi * 16;
                LDMATRIX_X4(a[mi][0], a[mi][1], a[mi][2], a[mi][3],
                            As + m * 128 + ((kq_a ^ (m & 7)) << 4));
            }
            uint32_t bq[2][4];
            #pragma unroll
            for (int q = 0; q < 2; ++q) {
                const int n = b_n + q * 16;
                LDMATRIX_X4(bq[q][0], bq[q][1], bq[q][2], bq[q][3],
                            Bs + n * 128 + ((kq_b ^ (n & 7)) << 4));
            }
            #pragma unroll
            for (int mi = 0; mi < 4; ++mi)
                #pragma unroll
                for (int q = 0; q < 2; ++q) {
                    mma_f16(acc[mi][2 * q + 0], a[mi], &bq[q][0]);
                    mma_f16(acc[mi][2 * q + 1], a[mi], &bq[q][2]);
                }
        }
        // ---- dx GEMM: dy rows only (wm==1 warps), same accumulators ----
        if (wm == 1) {
            const uint32_t Asd = As + OFF_ADX;
            const uint32_t Bsd = As + OFF_BDX;
            #pragma unroll
            for (int ks = 0; ks < 4; ++ks) {
                const int kq_a = ks * 2 + a_kq;
                const int kq_b = ks * 2 + b_kq;
                uint32_t a[4][4];
                #pragma unroll
                for (int mi = 0; mi < 4; ++mi) {
                    const int r = a_row + mi * 16;           // row-64 index
                    LDMATRIX_X4(a[mi][0], a[mi][1], a[mi][2], a[mi][3],
                                Asd + r * 128 + ((kq_a ^ (r & 7)) << 4));
                }
                uint32_t bq[2][4];
                #pragma unroll
                for (int q = 0; q < 2; ++q) {
                    const int n = b_n + q * 16;
                    LDMATRIX_X4(bq[q][0], bq[q][1], bq[q][2], bq[q][3],
                                Bsd + n * 128 + ((kq_b ^ (n & 7)) << 4));
                }
                #pragma unroll
                for (int mi = 0; mi < 4; ++mi)
                    #pragma unroll
                    for (int q = 0; q < 2; ++q) {
                        mma_f16(acc[mi][2 * q + 0], a[mi], &bq[q][0]);
                        mma_f16(acc[mi][2 * q + 1], a[mi], &bq[q][2]);
                    }
            }
        }
    }

    // ---- epilogue ----
    const size_t NOUT   = (size_t)DOUT * DOUT * DOUT;
    const size_t dy_off = (size_t)B_ * COUT * NOUT;
    const int m_base = wm * 64;
    const int n_base = wn * 32;

    #pragma unroll
    for (int mi = 0; mi < 4; ++mi) {
        #pragma unroll
        for (int h = 0; h < 2; ++h) {
            const int m  = m_base + mi * 16 + h * 8 + g;
            const bool isy = (m < 64);
            const int co = m & 63;
            const float bv = isy ? bias[co] : 0.f;
            const size_t outadd = isy ? 0 : dy_off;
            const size_t ob = ((size_t)(b * COUT + co) * DOUT + z0) * DOUT;
            #pragma unroll
            for (int ni = 0; ni < 4; ++ni) {
                const int n  = n_base + ni * 8 + ct * 2;
                const int yo = y0 + (n >> 6);       // < 62 always (31*2 grid)
                const int xo = n & 63;
                const size_t idx = (ob + yo) * DOUT + xo;
                if (xo < DOUT) {
                    out[outadd + idx]     = acc[mi][ni][h * 2 + 0] + bv;
                    out[outadd + idx + 1] = acc[mi][ni][h * 2 + 1] + bv;  // xo even
                }
            }
        }
    }
}

// ---------------------------------------------------------------------------
// Launch. Inputs: x, s, dx, style_weight, style_bias, weight, bias.
// Output: concat(y, dy) fp32.
// ---------------------------------------------------------------------------
extern "C" void kernel_launch(void* const* d_in, const int* in_sizes, int n_in,
                              void* d_out, int out_size)
{
    const float* x    = (const float*)d_in[0];
    const float* s    = (const float*)d_in[1];
    const float* dx   = (const float*)d_in[2];
    const float* sw   = (const float*)d_in[3];
    const float* sb   = (const float*)d_in[4];
    const float* w    = (const float*)d_in[5];
    const float* bias = (const float*)d_in[6];
    float* out = (float*)d_out;

    cudaFuncSetAttribute(conv_mma_kernel, cudaFuncAttributeMaxDynamicSharedMemorySize, SMEM_DYN);

    prep_kernel<<<B_ * COUT, 256>>>(s, sw, sb, w);
    zero_adx_kernel<<<B_ * KTAPS, 256>>>();
    transpose_kernel<<<dim3(64, 64, B_), dim3(32, 8)>>>(x, dx);
    conv_mma_kernel<<<dim3(31, 62, B_), 256, SMEM_DYN>>>(bias, out);
}